// round 7
// baseline (speedup 1.0000x reference)
#include <cuda_runtime.h>

#define NROWS 2048
#define DIN 256
#define H 64
#define HP 32   // h pairs
#define HQ 16   // h quads (2 pairs)

// Hidden activations, interleaved for the outer kernel:
// float4 entry [hq*2048 + n] = { h=4hq, 4hq+1, 4hq+2, 4hq+3 }
__device__ float4 g_agh[HQ * NROWS];
__device__ float4 g_abh[HQ * NROWS];

typedef unsigned long long u64;

__device__ __forceinline__ u64 f2add(u64 a, u64 b) {
    u64 d; asm("add.rn.f32x2 %0, %1, %2;" : "=l"(d) : "l"(a), "l"(b)); return d;
}
__device__ __forceinline__ u64 f2fma(u64 a, u64 b, u64 c) {
    u64 d; asm("fma.rn.f32x2 %0, %1, %2, %3;" : "=l"(d) : "l"(a), "l"(b), "l"(c)); return d;
}
__device__ __forceinline__ u64 f2relu(u64 s) {
    float lo, hi;
    asm("mov.b64 {%0, %1}, %2;" : "=f"(lo), "=f"(hi) : "l"(s));
    lo = fmaxf(lo, 0.0f);
    hi = fmaxf(hi, 0.0f);
    u64 d; asm("mov.b64 %0, {%1, %2};" : "=l"(d) : "f"(lo), "f"(hi)); return d;
}

// ---------------------------------------------------------------------------
// Kernel 1 (fused): hidden for BOTH embeddings.
// blocks [0,128) -> ag (+b1), [128,256) -> ab. 16 rows/block.
// Thread (hq = tid&15, rs = tid>>4): 1 row, 4 h (float4 acc).
// Per kk: 1 LDS.128 (w, conflict-free across hq) + 1 LDS.32 (e, broadcast)
// + 4 FFMA = 6 slots / 4 MAC. Store = one float4, matches outer layout.
// ---------------------------------------------------------------------------
__global__ void __launch_bounds__(256) hidden_kernel(
    const float* __restrict__ ag, const float* __restrict__ ab,
    const float* __restrict__ W1, const float* __restrict__ b1)
{
    __shared__ float  embs[16][128];    //  8 KB
    __shared__ float4 w1s[128][16];     // 32 KB (same linear layout as before)

    const int tid = threadIdx.x;
    const int hq  = tid & 15;
    const int rs  = tid >> 4;           // 0..15
    const int which = blockIdx.x >> 7;  // 0 = ag, 1 = ab
    const int n0  = (blockIdx.x & 127) * 16;
    const int koff = which ? DIN : 0;
    const float* __restrict__ emb = which ? ab : ag;

    float4 acc;
    if (which == 0) acc = ((const float4*)b1)[hq];
    else            acc = make_float4(0.f, 0.f, 0.f, 0.f);

    for (int kb = 0; kb < 2; kb++) {
        #pragma unroll
        for (int t = 0; t < 2; t++) {
            int idx = tid + t * 256, r = idx >> 5, c4 = idx & 31;
            ((float4*)&embs[r][c4 * 4])[0] =
                ((const float4*)(emb + (size_t)(n0 + r) * DIN + kb * 128))[c4];
        }
        #pragma unroll
        for (int t = 0; t < 8; t++) {
            int idx = tid + t * 256, kk = idx >> 4, q = idx & 15;
            w1s[kk][q] =
                ((const float4*)(W1 + (size_t)(koff + kb * 128 + kk) * H))[q];
        }
        __syncthreads();

        #pragma unroll 16
        for (int kk = 0; kk < 128; kk++) {
            float4 w = w1s[kk][hq];
            float e = embs[rs][kk];
            acc.x = fmaf(e, w.x, acc.x);
            acc.y = fmaf(e, w.y, acc.y);
            acc.z = fmaf(e, w.z, acc.z);
            acc.w = fmaf(e, w.w, acc.w);
        }
        __syncthreads();
    }

    float4* outh = which ? g_abh : g_agh;
    outh[(size_t)hq * NROWS + n0 + rs] = acc;
}

// ---------------------------------------------------------------------------
// Kernel 2: out[n,m] = sigmoid( sum_h relu(ag_h[n,h]+ab_h[m,h]) * W2[h] + b2 )
// 64x64 tile, 256 threads, 4x4 outputs/thread. Smem [hq][n] ulonglong2:
// coalesced 16B fill, loop = 9 LDS.128 + 128 math slots per hq, unroll 2
// (body < 6KB L0). launch_bounds(256,4) -> 64 regs, 4 blocks/SM.
// Epilogue uses __fdividef (MUFU.RCP) instead of IEEE division.
// ---------------------------------------------------------------------------
__global__ void __launch_bounds__(256, 4) outer_kernel(
    const float* __restrict__ W2, const float* __restrict__ b2,
    float* __restrict__ out)
{
    __shared__ ulonglong2 a_s[HQ][64];   // 16 KB
    __shared__ ulonglong2 b_s[HQ][64];   // 16 KB
    __shared__ float2 w2s[HP];

    const int tid = threadIdx.x;
    const int n0 = blockIdx.y * 64;
    const int m0 = blockIdx.x * 64;

    const ulonglong2* gA = (const ulonglong2*)g_agh;
    const ulonglong2* gB = (const ulonglong2*)g_abh;
    #pragma unroll
    for (int t = 0; t < 4; t++) {
        int idx = tid + t * 256;            // 0..1023
        int hq = idx >> 6, r = idx & 63;
        a_s[hq][r] = gA[(size_t)hq * NROWS + n0 + r];
        b_s[hq][r] = gB[(size_t)hq * NROWS + m0 + r];
    }
    if (tid < HP) w2s[tid] = ((const float2*)W2)[tid];
    __syncthreads();

    const int tx = tid & 15;   // m: m_local = tx + 16*j
    const int ty = tid >> 4;   // n: n_local = ty*4 + i
    const ulonglong2* w2q = (const ulonglong2*)w2s;

    u64 acc[4][4];
    #pragma unroll
    for (int i = 0; i < 4; i++)
        #pragma unroll
        for (int j = 0; j < 4; j++) acc[i][j] = 0ull;

    #pragma unroll 2
    for (int hq = 0; hq < HQ; hq++) {
        ulonglong2 wv = w2q[hq];
        ulonglong2 b[4];
        #pragma unroll
        for (int j = 0; j < 4; j++) b[j] = b_s[hq][tx + 16 * j];
        #pragma unroll
        for (int i = 0; i < 4; i++) {
            ulonglong2 av = a_s[hq][ty * 4 + i];
            #pragma unroll
            for (int j = 0; j < 4; j++) {
                acc[i][j] = f2fma(f2relu(f2add(av.x, b[j].x)), wv.x, acc[i][j]);
                acc[i][j] = f2fma(f2relu(f2add(av.y, b[j].y)), wv.y, acc[i][j]);
            }
        }
    }

    const float b2v = *b2;
    #pragma unroll
    for (int i = 0; i < 4; i++) {
        int n = n0 + ty * 4 + i;
        #pragma unroll
        for (int j = 0; j < 4; j++) {
            float lo, hi;
            asm("mov.b64 {%0, %1}, %2;" : "=f"(lo), "=f"(hi) : "l"(acc[i][j]));
            float logit = lo + hi + b2v;
            out[(size_t)n * 2048 + m0 + tx + 16 * j] =
                __fdividef(1.0f, 1.0f + __expf(-logit));
        }
    }
}

extern "C" void kernel_launch(void* const* d_in, const int* in_sizes, int n_in,
                              void* d_out, int out_size)
{
    const float* ag = (const float*)d_in[0];
    const float* ab = (const float*)d_in[1];
    const float* W1 = (const float*)d_in[2];
    const float* b1 = (const float*)d_in[3];
    const float* W2 = (const float*)d_in[4];
    const float* b2 = (const float*)d_in[5];
    float* out = (float*)d_out;

    hidden_kernel<<<256, 256>>>(ag, ab, W1, b1);

    dim3 grid(2048 / 64, 2048 / 64);
    outer_kernel<<<grid, 256>>>(W2, b2, out);
}

// round 8
// speedup vs baseline: 1.1285x; 1.1285x over previous
#include <cuda_runtime.h>

#define NROWS 2048
#define DIN 256
#define H 64
#define HP 32   // h pairs
#define HQ 16   // h quads (2 pairs)

// Hidden activations, interleaved for the outer kernel:
// ulonglong2 entry [hq*2048 + n] = { float2(h=4hq,4hq+1), float2(h=4hq+2,4hq+3) }
__device__ ulonglong2 g_agh[HQ * NROWS];
__device__ ulonglong2 g_abh[HQ * NROWS];

typedef unsigned long long u64;

__device__ __forceinline__ u64 f2add(u64 a, u64 b) {
    u64 d; asm("add.rn.f32x2 %0, %1, %2;" : "=l"(d) : "l"(a), "l"(b)); return d;
}
__device__ __forceinline__ u64 f2fma(u64 a, u64 b, u64 c) {
    u64 d; asm("fma.rn.f32x2 %0, %1, %2, %3;" : "=l"(d) : "l"(a), "l"(b), "l"(c)); return d;
}
__device__ __forceinline__ u64 f2relu(u64 s) {
    float lo, hi;
    asm("mov.b64 {%0, %1}, %2;" : "=f"(lo), "=f"(hi) : "l"(s));
    lo = fmaxf(lo, 0.0f);
    hi = fmaxf(hi, 0.0f);
    u64 d; asm("mov.b64 %0, {%1, %2};" : "=l"(d) : "f"(lo), "f"(hi)); return d;
}

// ---------------------------------------------------------------------------
// Kernel 1 (fused): hidden for BOTH embeddings (R6-proven body).
// blocks [0,128) -> ag (+b1), [128,256) -> ab. 16 rows/block.
// Thread: hp = tid&31, rows ng, ng+8. K tiled by 128.
// Stores go to the interleaved [hq][n] layout (float2 halves of ulonglong2).
// ---------------------------------------------------------------------------
__global__ void __launch_bounds__(256) hidden_kernel(
    const float* __restrict__ ag, const float* __restrict__ ab,
    const float* __restrict__ W1, const float* __restrict__ b1)
{
    __shared__ float  embs[16][128];    //  8 KB
    __shared__ float2 w1s[128][32];     // 32 KB

    const int tid = threadIdx.x;
    const int hp  = tid & 31;
    const int ng  = tid >> 5;           // 0..7
    const int which = blockIdx.x >> 7;  // 0 = ag, 1 = ab
    const int n0  = (blockIdx.x & 127) * 16;
    const int koff = which ? DIN : 0;
    const float* __restrict__ emb = which ? ab : ag;

    float acc00, acc01, acc10, acc11;
    if (which == 0) {
        float2 bv = ((const float2*)b1)[hp];
        acc00 = bv.x; acc01 = bv.y; acc10 = bv.x; acc11 = bv.y;
    } else {
        acc00 = acc01 = acc10 = acc11 = 0.0f;
    }

    for (int kb = 0; kb < 2; kb++) {
        #pragma unroll
        for (int t = 0; t < 2; t++) {
            int idx = tid + t * 256, r = idx >> 5, c4 = idx & 31;
            ((float4*)&embs[r][c4 * 4])[0] =
                ((const float4*)(emb + (size_t)(n0 + r) * DIN + kb * 128))[c4];
        }
        #pragma unroll
        for (int t = 0; t < 8; t++) {
            int idx = tid + t * 256, kk = idx >> 4, q = idx & 15;
            ((float4*)&w1s[kk][0])[q] =
                ((const float4*)(W1 + (size_t)(koff + kb * 128 + kk) * H))[q];
        }
        __syncthreads();

        #pragma unroll 16
        for (int kk = 0; kk < 128; kk++) {
            float2 w = w1s[kk][hp];
            float e0 = embs[ng][kk];
            float e1 = embs[ng + 8][kk];
            acc00 += e0 * w.x;  acc01 += e0 * w.y;
            acc10 += e1 * w.x;  acc11 += e1 * w.y;
        }
        __syncthreads();
    }

    // interleaved store: float2 half (hp&1) of entry [hp>>1][n]
    float2* outh = (float2*)(which ? g_abh : g_agh);
    size_t base = (size_t)(hp >> 1) * NROWS;
    outh[(base + n0 + ng)     * 2 + (hp & 1)] = make_float2(acc00, acc01);
    outh[(base + n0 + ng + 8) * 2 + (hp & 1)] = make_float2(acc10, acc11);
}

// ---------------------------------------------------------------------------
// Kernel 2: out[n,m] = sigmoid( sum_h relu(ag_h[n,h]+ab_h[m,h]) * W2[h] + b2 )
// 64x64 tile, 256 threads, 4x4 outputs/thread. Smem [hq][n] ulonglong2:
// coalesced 16B fill, loop = 9 LDS.128 + 128 math slots per hq, unroll 2
// (body < 6KB L0). Natural regs (NO launch-bounds cap — caps spill).
// Epilogue: __fdividef (MUFU.RCP) instead of IEEE division.
// ---------------------------------------------------------------------------
__global__ void __launch_bounds__(256) outer_kernel(
    const float* __restrict__ W2, const float* __restrict__ b2,
    float* __restrict__ out)
{
    __shared__ ulonglong2 a_s[HQ][64];   // 16 KB
    __shared__ ulonglong2 b_s[HQ][64];   // 16 KB
    __shared__ float2 w2s[HP];

    const int tid = threadIdx.x;
    const int n0 = blockIdx.y * 64;
    const int m0 = blockIdx.x * 64;

    #pragma unroll
    for (int t = 0; t < 4; t++) {
        int idx = tid + t * 256;            // 0..1023
        int hq = idx >> 6, r = idx & 63;
        a_s[hq][r] = g_agh[(size_t)hq * NROWS + n0 + r];
        b_s[hq][r] = g_abh[(size_t)hq * NROWS + m0 + r];
    }
    if (tid < HP) w2s[tid] = ((const float2*)W2)[tid];
    __syncthreads();

    const int tx = tid & 15;   // m: m_local = tx + 16*j
    const int ty = tid >> 4;   // n: n_local = ty*4 + i
    const ulonglong2* w2q = (const ulonglong2*)w2s;

    u64 acc[4][4];
    #pragma unroll
    for (int i = 0; i < 4; i++)
        #pragma unroll
        for (int j = 0; j < 4; j++) acc[i][j] = 0ull;

    #pragma unroll 2
    for (int hq = 0; hq < HQ; hq++) {
        ulonglong2 wv = w2q[hq];
        ulonglong2 b[4];
        #pragma unroll
        for (int j = 0; j < 4; j++) b[j] = b_s[hq][tx + 16 * j];
        #pragma unroll
        for (int i = 0; i < 4; i++) {
            ulonglong2 av = a_s[hq][ty * 4 + i];
            #pragma unroll
            for (int j = 0; j < 4; j++) {
                acc[i][j] = f2fma(f2relu(f2add(av.x, b[j].x)), wv.x, acc[i][j]);
                acc[i][j] = f2fma(f2relu(f2add(av.y, b[j].y)), wv.y, acc[i][j]);
            }
        }
    }

    const float b2v = *b2;
    #pragma unroll
    for (int i = 0; i < 4; i++) {
        int n = n0 + ty * 4 + i;
        #pragma unroll
        for (int j = 0; j < 4; j++) {
            float lo, hi;
            asm("mov.b64 {%0, %1}, %2;" : "=f"(lo), "=f"(hi) : "l"(acc[i][j]));
            float logit = lo + hi + b2v;
            out[(size_t)n * 2048 + m0 + tx + 16 * j] =
                __fdividef(1.0f, 1.0f + __expf(-logit));
        }
    }
}

extern "C" void kernel_launch(void* const* d_in, const int* in_sizes, int n_in,
                              void* d_out, int out_size)
{
    const float* ag = (const float*)d_in[0];
    const float* ab = (const float*)d_in[1];
    const float* W1 = (const float*)d_in[2];
    const float* b1 = (const float*)d_in[3];
    const float* W2 = (const float*)d_in[4];
    const float* b2 = (const float*)d_in[5];
    float* out = (float*)d_out;

    hidden_kernel<<<256, 256>>>(ag, ab, W1, b1);

    dim3 grid(2048 / 64, 2048 / 64);
    outer_kernel<<<grid, 256>>>(W2, b2, out);
}

// round 13
// speedup vs baseline: 1.3158x; 1.1660x over previous
#include <cuda_runtime.h>
#include <cuda_fp16.h>

#define NROWS 2048
#define DIN 256
#define H 64
#define HP 32   // h pairs

// Hidden activations in fp16, packed 8-per-entry:
// uint4 entry [ho*2048 + n], ho=0..7, holds h = 8ho..8ho+7 as 4 half2.
__device__ uint4 g_agh[8 * NROWS];
__device__ uint4 g_abh[8 * NROWS];

// ---------------------------------------------------------------------------
// Kernel 1 (fused): hidden for BOTH embeddings (R6/R8-proven fp32 body).
// blocks [0,128) -> ag (+b1), [128,256) -> ab. 16 rows/block.
// Thread: hp = tid&31, rows ng, ng+8. K tiled by 128. fp32 compute,
// outputs converted to half2 and stored into the packed uint4 layout.
// ---------------------------------------------------------------------------
__global__ void __launch_bounds__(256) hidden_kernel(
    const float* __restrict__ ag, const float* __restrict__ ab,
    const float* __restrict__ W1, const float* __restrict__ b1)
{
    __shared__ float  embs[16][128];    //  8 KB
    __shared__ float2 w1s[128][32];     // 32 KB

    const int tid = threadIdx.x;
    const int hp  = tid & 31;
    const int ng  = tid >> 5;           // 0..7
    const int which = blockIdx.x >> 7;  // 0 = ag, 1 = ab
    const int n0  = (blockIdx.x & 127) * 16;
    const int koff = which ? DIN : 0;
    const float* __restrict__ emb = which ? ab : ag;

    float acc00, acc01, acc10, acc11;
    if (which == 0) {
        float2 bv = ((const float2*)b1)[hp];
        acc00 = bv.x; acc01 = bv.y; acc10 = bv.x; acc11 = bv.y;
    } else {
        acc00 = acc01 = acc10 = acc11 = 0.0f;
    }

    for (int kb = 0; kb < 2; kb++) {
        #pragma unroll
        for (int t = 0; t < 2; t++) {
            int idx = tid + t * 256, r = idx >> 5, c4 = idx & 31;
            ((float4*)&embs[r][c4 * 4])[0] =
                ((const float4*)(emb + (size_t)(n0 + r) * DIN + kb * 128))[c4];
        }
        #pragma unroll
        for (int t = 0; t < 8; t++) {
            int idx = tid + t * 256, kk = idx >> 4, q = idx & 15;
            ((float4*)&w1s[kk][0])[q] =
                ((const float4*)(W1 + (size_t)(koff + kb * 128 + kk) * H))[q];
        }
        __syncthreads();

        #pragma unroll 16
        for (int kk = 0; kk < 128; kk++) {
            float2 w = w1s[kk][hp];
            float e0 = embs[ng][kk];
            float e1 = embs[ng + 8][kk];
            acc00 += e0 * w.x;  acc01 += e0 * w.y;
            acc10 += e1 * w.x;  acc11 += e1 * w.y;
        }
        __syncthreads();
    }

    // pack to half2 and store into uint word (hp&3) of entry [hp>>2][n]
    unsigned* outh = (unsigned*)(which ? g_abh : g_agh);
    const unsigned wbase = (unsigned)(hp >> 2) * (NROWS * 4) + (hp & 3);
    __half2 v0 = __floats2half2_rn(acc00, acc01);
    __half2 v1 = __floats2half2_rn(acc10, acc11);
    outh[wbase + (unsigned)(n0 + ng) * 4]       = *(unsigned*)&v0;
    outh[wbase + (unsigned)(n0 + ng + 8) * 4]   = *(unsigned*)&v1;
}

// ---------------------------------------------------------------------------
// Kernel 2 (fp16 packed): out[n,m] = sigmoid( sum_h relu(agh+abh)*W2 + b2 )
// 64x64 tile, 256 threads, 4x4 outputs/thread. Smem [ho][n] uint4 (8 h per
// entry): coalesced fill; per ho: 9 LDS.128 + 192 packed half2 math slots.
// Two accumulator sets (ho 0-3 / 4-7) combined in fp32 to bound fp16
// accumulation error. Epilogue: __fdividef + __expf.
// ---------------------------------------------------------------------------
struct H2x4 { __half2 h0, h1, h2, h3; };

__device__ __forceinline__ void outer_body(
    __half2 (&acc)[4][4], int ho, int tx, int ty,
    const uint4 (*a_s)[64], const uint4 (*b_s)[64], const uint4* w2q,
    __half2 z)
{
    uint4 wv = w2q[ho];
    const H2x4 w = *(const H2x4*)&wv;
    uint4 bb[4];
    #pragma unroll
    for (int j = 0; j < 4; j++) bb[j] = b_s[ho][tx + 16 * j];
    #pragma unroll
    for (int i = 0; i < 4; i++) {
        uint4 av = a_s[ho][ty * 4 + i];
        const H2x4 a = *(const H2x4*)&av;
        #pragma unroll
        for (int j = 0; j < 4; j++) {
            const H2x4 b = *(const H2x4*)&bb[j];
            acc[i][j] = __hfma2(__hmax2(__hadd2(a.h0, b.h0), z), w.h0, acc[i][j]);
            acc[i][j] = __hfma2(__hmax2(__hadd2(a.h1, b.h1), z), w.h1, acc[i][j]);
            acc[i][j] = __hfma2(__hmax2(__hadd2(a.h2, b.h2), z), w.h2, acc[i][j]);
            acc[i][j] = __hfma2(__hmax2(__hadd2(a.h3, b.h3), z), w.h3, acc[i][j]);
        }
    }
}

__global__ void __launch_bounds__(256) outer_kernel(
    const float* __restrict__ W2, const float* __restrict__ b2,
    float* __restrict__ out)
{
    __shared__ uint4 a_s[8][64];     // 4 KB
    __shared__ uint4 b_s[8][64];     // 4 KB
    __shared__ __half2 w2s[HP];      // 128 B

    const int tid = threadIdx.x;
    const int n0 = blockIdx.y * 64;
    const int m0 = blockIdx.x * 64;

    #pragma unroll
    for (int t = 0; t < 2; t++) {
        int idx = tid + t * 256;            // 0..511
        int ho = idx >> 6, r = idx & 63;
        a_s[ho][r] = g_agh[ho * NROWS + n0 + r];
        b_s[ho][r] = g_abh[ho * NROWS + m0 + r];
    }
    if (tid < HP) w2s[tid] = __floats2half2_rn(W2[2 * tid], W2[2 * tid + 1]);
    __syncthreads();

    const int tx = tid & 15;   // m: m_local = tx + 16*j
    const int ty = tid >> 4;   // n: n_local = ty*4 + i
    const uint4* w2q = (const uint4*)w2s;
    const __half2 z = __float2half2_rn(0.0f);

    __half2 acc0[4][4], acc1[4][4];
    #pragma unroll
    for (int i = 0; i < 4; i++)
        #pragma unroll
        for (int j = 0; j < 4; j++) { acc0[i][j] = z; acc1[i][j] = z; }

    #pragma unroll 1
    for (int ho = 0; ho < 4; ho++)
        outer_body(acc0, ho, tx, ty, a_s, b_s, w2q, z);
    #pragma unroll 1
    for (int ho = 4; ho < 8; ho++)
        outer_body(acc1, ho, tx, ty, a_s, b_s, w2q, z);

    const float b2v = *b2;
    #pragma unroll
    for (int i = 0; i < 4; i++) {
        int n = n0 + ty * 4 + i;
        #pragma unroll
        for (int j = 0; j < 4; j++) {
            float2 p = __half22float2(acc0[i][j]);
            float2 q = __half22float2(acc1[i][j]);
            float logit = ((p.x + q.x) + (p.y + q.y)) + b2v;
            out[(size_t)n * 2048 + m0 + tx + 16 * j] =
                __fdividef(1.0f, 1.0f + __expf(-logit));
        }
    }
}

extern "C" void kernel_launch(void* const* d_in, const int* in_sizes, int n_in,
                              void* d_out, int out_size)
{
    const float* ag = (const float*)d_in[0];
    const float* ab = (const float*)d_in[1];
    const float* W1 = (const float*)d_in[2];
    const float* b1 = (const float*)d_in[3];
    const float* W2 = (const float*)d_in[4];
    const float* b2 = (const float*)d_in[5];
    float* out = (float*)d_out;

    hidden_kernel<<<256, 256>>>(ag, ab, W1, b1);

    dim3 grid(2048 / 64, 2048 / 64);
    outer_kernel<<<grid, 256>>>(W2, b2, out);
}